// round 14
// baseline (speedup 1.0000x reference)
#include <cuda_runtime.h>
#include <math.h>

#define BB 4
#define HH 512
#define WW 512
#define NUM_INST 32
#define EPS 1e-5f
#define MAXB 256

// Raw ping-pong activation buffers (max 4*16*512*512 floats = 64MB each)
__device__ float g_bufA[BB * 16 * HH * WW];
__device__ float g_bufB[BB * 16 * HH * WW];
// Normalized + padded input buffer (max 4*16*518*518 floats ~ 68.7MB)
__device__ float g_bufP[BB * 16 * 520 * 520];
// Per-(plane,block) stats partials (sum, sumsq)
__device__ float2 g_ps[BB * 256 * MAXB];
__device__ float g_means[NUM_INST * 3];
__device__ float g_part[NUM_INST * 8 * 4];

__device__ __forceinline__ int refl(int i, int n) {
    return i < 0 ? -i : (i >= n ? 2 * n - 2 - i : i);
}

// ---------------------------------------------------------------------------
// normpad: finalize per-plane stats from partials, write relu((x-m)*rs) into
// a padded plane. P border: zeros (reflect=0) or reflect (reflect=1).
// grid = (rows Hp, planes). Memory-bound.
// ---------------------------------------------------------------------------
__global__ void normpad_k(const float* __restrict__ y, float* __restrict__ xp,
                          int H, int W, int P, int reflect, int nblk, float invHW) {
    int plane = blockIdx.y;
    int Hp = H + 2 * P, Wp = W + 2 * P;
    __shared__ float smv[2];
    if (threadIdx.x < 32) {
        float s = 0.f, q = 0.f;
        const float2* pp = g_ps + (size_t)plane * MAXB;
        for (int i = threadIdx.x; i < nblk; i += 32) {
            float2 v = pp[i];
            s += v.x;
            q += v.y;
        }
        for (int o = 16; o; o >>= 1) {
            s += __shfl_down_sync(0xffffffffu, s, o);
            q += __shfl_down_sync(0xffffffffu, q, o);
        }
        if (threadIdx.x == 0) {
            float m = s * invHW;
            float var = q * invHW - m * m;
            smv[0] = m;
            smv[1] = rsqrtf(var + EPS);
        }
    }
    __syncthreads();
    float m = smv[0], rs = smv[1];
    const float* ypl = y + (size_t)plane * H * W;
    float* xpl = xp + (size_t)plane * Hp * Wp;

    for (int hp = blockIdx.x; hp < Hp; hp += gridDim.x) {
        int h = hp - P;
        bool hv = true;
        if (reflect) h = refl(h, H);
        else hv = (unsigned)h < (unsigned)H;
        const float* row = ypl + (size_t)(hv ? h : 0) * W;
        float* orow = xpl + (size_t)hp * Wp;
        for (int wp0 = threadIdx.x; wp0 < Wp; wp0 += blockDim.x) {
            int wc = wp0 - P;
            bool v = hv;
            if (reflect) wc = refl(wc, W);
            else v = v && (unsigned)wc < (unsigned)W;
            float raw = v ? row[wc] : 0.f;
            orow[wp0] = v ? fmaxf((raw - m) * rs, 0.f) : 0.f;
        }
    }
}

// ---------------------------------------------------------------------------
// 3x3 stride-2 conv over PRE-NORMALIZED PADDED input (P=1). TS=2 fixed.
// Thread = 2x2 outputs x COPT channels. Flat inner loop: 25 plain LDG off one
// base pointer + 9*V LDS.128 + 36*COPT FMA, no predicates, no norm math.
// Fused stats partials on OUTPUT into g_ps.
// ---------------------------------------------------------------------------
template <int CIN, int COUT, int COPT, int HIN, int WIN, int NT>
__global__ void __launch_bounds__(NT) conv_s2_t(const float* __restrict__ xpad,
                                                const float* __restrict__ w,
                                                const float* __restrict__ bias,
                                                float* __restrict__ y) {
    constexpr int HOUT = HIN / 2, WOUT = WIN / 2;
    constexpr int TW = WOUT / 2;
    constexpr int WP = WIN + 2;
    constexpr int PS = (HIN + 2) * WP;
    constexpr int CHUNK = (CIN < 64) ? CIN : 64;
    constexpr int V = COPT / 4;
    __shared__ __align__(16) float wsm[CHUNK * 9 * COPT];
    __shared__ float ssm[NT / 32][COPT], qsm[NT / 32][COPT];

    int t = blockIdx.x * NT + threadIdx.x;
    int cog = blockIdx.y % (COUT / COPT);
    int n = blockIdx.y / (COUT / COPT);
    int oh0 = (t / TW) * 2, ow0 = (t % TW) * 2;
    int lane = threadIdx.x & 31, wrp = threadIdx.x >> 5;

    float acc[4 * COPT];
#pragma unroll
    for (int i = 0; i < 4 * COPT; i++) acc[i] = 0.f;

    const float* xbase = xpad + (size_t)n * CIN * PS + (size_t)(oh0 * 2) * WP + ow0 * 2;

#pragma unroll 1
    for (int c0 = 0; c0 < CIN; c0 += CHUNK) {
        __syncthreads();
        for (int i = threadIdx.x; i < CHUNK * 9 * COPT; i += NT) {
            int ci_l = i / (9 * COPT);
            int rem = i - ci_l * (9 * COPT);
            int tap = rem / COPT;
            int u = rem - tap * COPT;
            wsm[i] = w[((size_t)(cog * COPT + u) * CIN + c0 + ci_l) * 9 + tap];
        }
        __syncthreads();
#pragma unroll 1
        for (int ci_l = 0; ci_l < CHUNK; ci_l++) {
            const float* xp = xbase + (size_t)(c0 + ci_l) * PS;

            // flat 25-load batch, no predicates
            float xv[25];
#pragma unroll
            for (int r = 0; r < 5; r++)
#pragma unroll
                for (int c = 0; c < 5; c++)
                    xv[r * 5 + c] = xp[r * WP + c];

            const float4* wp4 = reinterpret_cast<const float4*>(wsm + ci_l * 9 * COPT);
#pragma unroll
            for (int kh = 0; kh < 3; kh++) {
#pragma unroll
                for (int kw = 0; kw < 3; kw++) {
#pragma unroll
                    for (int v = 0; v < V; v++) {
                        float4 wq = wp4[(kh * 3 + kw) * V + v];
                        float wa[4] = {wq.x, wq.y, wq.z, wq.w};
#pragma unroll
                        for (int j = 0; j < 4; j++) {
#pragma unroll
                            for (int orow = 0; orow < 2; orow++)
#pragma unroll
                                for (int oc = 0; oc < 2; oc++)
                                    acc[(orow * 2 + oc) * COPT + v * 4 + j] =
                                        fmaf(xv[(2 * orow + kh) * 5 + 2 * oc + kw], wa[j],
                                             acc[(orow * 2 + oc) * COPT + v * 4 + j]);
                        }
                    }
                }
            }
        }
    }
    // bias
#pragma unroll
    for (int u = 0; u < COPT; u++) {
        float bv = bias[cog * COPT + u];
#pragma unroll
        for (int p = 0; p < 4; p++) acc[p * COPT + u] += bv;
    }
    // stores
    size_t obase = (size_t)(n * COUT + cog * COPT) * HOUT * WOUT + (size_t)oh0 * WOUT + ow0;
#pragma unroll
    for (int u = 0; u < COPT; u++) {
#pragma unroll
        for (int orow = 0; orow < 2; orow++) {
            float* yp = y + obase + (size_t)u * HOUT * WOUT + (size_t)orow * WOUT;
            float2 v;
            v.x = acc[(orow * 2 + 0) * COPT + u];
            v.y = acc[(orow * 2 + 1) * COPT + u];
            *reinterpret_cast<float2*>(yp) = v;
        }
    }
    // fused stats partial (deterministic)
#pragma unroll
    for (int u = 0; u < COPT; u++) {
        float s = 0.f, q = 0.f;
#pragma unroll
        for (int p = 0; p < 4; p++) {
            float v = acc[p * COPT + u];
            s += v;
            q += v * v;
        }
        for (int o = 16; o; o >>= 1) {
            s += __shfl_down_sync(0xffffffffu, s, o);
            q += __shfl_down_sync(0xffffffffu, q, o);
        }
        if (lane == 0) { ssm[wrp][u] = s; qsm[wrp][u] = q; }
    }
    __syncthreads();
    if (threadIdx.x < COPT) {
        float s = 0.f, q = 0.f;
#pragma unroll
        for (int wpp = 0; wpp < NT / 32; wpp++) { s += ssm[wpp][threadIdx.x]; q += qsm[wpp][threadIdx.x]; }
        int plane = n * COUT + cog * COPT + threadIdx.x;
        g_ps[(size_t)plane * MAXB + blockIdx.x] = make_float2(s, q);
    }
}

// ---------------------------------------------------------------------------
// ConvTranspose2d k=3 s=2 p=1 op=1 over PRE-NORMALIZED PADDED input (P=1).
// TS x TS tile, weight layout (CIN, COUT, 3, 3). No predicates, no norm math.
// ---------------------------------------------------------------------------
template <int CIN, int COUT, int COPT, int TS, int HIN, int WIN, int NT>
__global__ void __launch_bounds__(NT) deconv_t(const float* __restrict__ xpad,
                                               const float* __restrict__ w,
                                               const float* __restrict__ bias,
                                               float* __restrict__ y) {
    constexpr int HOUT = HIN * 2, WOUT = WIN * 2;
    constexpr int TW = WOUT / TS;
    constexpr int SUB = TS / 2;
    constexpr int WP = WIN + 2;
    constexpr int PS = (HIN + 2) * WP;
    constexpr int CHUNK = (CIN < 64) ? CIN : 64;
    constexpr int V = COPT / 4;
    __shared__ __align__(16) float wsm[CHUNK * 9 * COPT];
    __shared__ float ssm[NT / 32][COPT], qsm[NT / 32][COPT];

    int t = blockIdx.x * NT + threadIdx.x;
    int cog = blockIdx.y % (COUT / COPT);
    int n = blockIdx.y / (COUT / COPT);
    int oh0 = (t / TW) * TS, ow0 = (t % TW) * TS;
    int i0 = oh0 >> 1, j0 = ow0 >> 1;
    int lane = threadIdx.x & 31, wrp = threadIdx.x >> 5;

    float acc[TS * TS * COPT];
#pragma unroll
    for (int i = 0; i < TS * TS * COPT; i++) acc[i] = 0.f;

    const float* xbase = xpad + (size_t)n * CIN * PS + (size_t)(i0 + 1) * WP + (j0 + 1);

#pragma unroll 1
    for (int c0 = 0; c0 < CIN; c0 += CHUNK) {
        __syncthreads();
        for (int i = threadIdx.x; i < CHUNK * 9 * COPT; i += NT) {
            int ci_l = i / (9 * COPT);
            int rem = i - ci_l * (9 * COPT);
            int tap = rem / COPT;
            int u = rem - tap * COPT;
            wsm[i] = w[((size_t)(c0 + ci_l) * COUT + cog * COPT + u) * 9 + tap];
        }
        __syncthreads();
#pragma unroll 1
        for (int ci_l = 0; ci_l < CHUNK; ci_l++) {
            const float* xp = xbase + (size_t)(c0 + ci_l) * PS;
            float xr[(SUB + 1) * (SUB + 1)];
#pragma unroll
            for (int r = 0; r <= SUB; r++)
#pragma unroll
                for (int c = 0; c <= SUB; c++)
                    xr[r * (SUB + 1) + c] = xp[r * WP + c];

#pragma unroll
            for (int kh = 0; kh < 3; kh++) {
                int orl = (kh == 1) ? 0 : 1;
                int xro = (kh == 0) ? 1 : 0;
#pragma unroll
                for (int kw = 0; kw < 3; kw++) {
                    int ocl = (kw == 1) ? 0 : 1;
                    int xco = (kw == 0) ? 1 : 0;
                    const float4* wp4 =
                        reinterpret_cast<const float4*>(wsm + (ci_l * 9 + kh * 3 + kw) * COPT);
#pragma unroll
                    for (int v = 0; v < V; v++) {
                        float4 wq = wp4[v];
                        float wa[4] = {wq.x, wq.y, wq.z, wq.w};
#pragma unroll
                        for (int j = 0; j < 4; j++) {
#pragma unroll
                            for (int a = 0; a < SUB; a++)
#pragma unroll
                                for (int b = 0; b < SUB; b++)
                                    acc[((2 * a + orl) * TS + (2 * b + ocl)) * COPT + v * 4 + j] =
                                        fmaf(xr[(a + xro) * (SUB + 1) + (b + xco)], wa[j],
                                             acc[((2 * a + orl) * TS + (2 * b + ocl)) * COPT + v * 4 + j]);
                        }
                    }
                }
            }
        }
    }
#pragma unroll
    for (int u = 0; u < COPT; u++) {
        float bv = bias[cog * COPT + u];
#pragma unroll
        for (int p = 0; p < TS * TS; p++) acc[p * COPT + u] += bv;
    }
    size_t obase = (size_t)(n * COUT + cog * COPT) * HOUT * WOUT + (size_t)oh0 * WOUT + ow0;
#pragma unroll
    for (int u = 0; u < COPT; u++) {
#pragma unroll
        for (int orow = 0; orow < TS; orow++) {
            float* yp = y + obase + (size_t)u * HOUT * WOUT + (size_t)orow * WOUT;
            float2 v;
            v.x = acc[(orow * TS + 0) * COPT + u];
            v.y = acc[(orow * TS + 1) * COPT + u];
            *reinterpret_cast<float2*>(yp) = v;
        }
    }
#pragma unroll
    for (int u = 0; u < COPT; u++) {
        float s = 0.f, q = 0.f;
#pragma unroll
        for (int p = 0; p < TS * TS; p++) {
            float v = acc[p * COPT + u];
            s += v;
            q += v * v;
        }
        for (int o = 16; o; o >>= 1) {
            s += __shfl_down_sync(0xffffffffu, s, o);
            q += __shfl_down_sync(0xffffffffu, q, o);
        }
        if (lane == 0) { ssm[wrp][u] = s; qsm[wrp][u] = q; }
    }
    __syncthreads();
    if (threadIdx.x < COPT) {
        float s = 0.f, q = 0.f;
#pragma unroll
        for (int wpp = 0; wpp < NT / 32; wpp++) { s += ssm[wpp][threadIdx.x]; q += qsm[wpp][threadIdx.x]; }
        int plane = n * COUT + cog * COPT + threadIdx.x;
        g_ps[(size_t)plane * MAXB + blockIdx.x] = make_float2(s, q);
    }
}

// ---------------------------------------------------------------------------
// conv0: reflect-pad 3, 7x7, 3->16. Thread = 1 row x 4 cols, all 16 co.
// Reads raw global input (reflect handled inline; only 3 channels).
// ---------------------------------------------------------------------------
__global__ void __launch_bounds__(256) conv7_first(const float* __restrict__ x,
                                                   const float* __restrict__ w,
                                                   const float* __restrict__ bias,
                                                   float* __restrict__ y) {
    __shared__ __align__(16) float wsm[3 * 49 * 16];
    __shared__ float ssm[8][16], qsm[8][16];
    for (int i = threadIdx.x; i < 3 * 49 * 16; i += 256) {
        int ci = i / (49 * 16);
        int rem = i - ci * (49 * 16);
        int tap = rem / 16;
        int co = rem - tap * 16;
        wsm[i] = w[(co * 3 + ci) * 49 + tap];
    }
    __syncthreads();

    int t = blockIdx.x * 256 + threadIdx.x;
    int n = blockIdx.y;
    int oh = t >> 7;
    int ow0 = (t & 127) * 4;

    int iwI[10];
#pragma unroll
    for (int c = 0; c < 10; c++) iwI[c] = refl(ow0 - 3 + c, WW);
    bool wInt = (ow0 >= 4) && (ow0 + 7 <= WW - 1);

    float acc[4 * 16];
#pragma unroll
    for (int i = 0; i < 4 * 16; i++) acc[i] = 0.f;

#pragma unroll 1
    for (int ci = 0; ci < 3; ci++) {
        const float* xp = x + (size_t)(n * 3 + ci) * HH * WW;
#pragma unroll 1
        for (int kh = 0; kh < 7; kh++) {
            const float* xr = xp + (size_t)refl(oh + kh - 3, HH) * WW;
            float xv[10];
            if (wInt) {
                const float* b = xr + ow0;
                float4 qa = *reinterpret_cast<const float4*>(b - 4);
                float4 qb = *reinterpret_cast<const float4*>(b);
                float4 qc = *reinterpret_cast<const float4*>(b + 4);
                xv[0] = qa.y; xv[1] = qa.z; xv[2] = qa.w;
                xv[3] = qb.x; xv[4] = qb.y; xv[5] = qb.z; xv[6] = qb.w;
                xv[7] = qc.x; xv[8] = qc.y; xv[9] = qc.z;
            } else {
#pragma unroll
                for (int c = 0; c < 10; c++) xv[c] = xr[iwI[c]];
            }
            const float4* wb4 = reinterpret_cast<const float4*>(wsm + (ci * 49 + kh * 7) * 16);
#pragma unroll
            for (int kw = 0; kw < 7; kw++) {
#pragma unroll
                for (int v = 0; v < 4; v++) {
                    float4 wq = wb4[kw * 4 + v];
                    float wa[4] = {wq.x, wq.y, wq.z, wq.w};
#pragma unroll
                    for (int j = 0; j < 4; j++) {
#pragma unroll
                        for (int sc = 0; sc < 4; sc++)
                            acc[sc * 16 + v * 4 + j] = fmaf(xv[sc + kw], wa[j], acc[sc * 16 + v * 4 + j]);
                    }
                }
            }
        }
    }
#pragma unroll
    for (int co = 0; co < 16; co++) {
        float bv = bias[co];
#pragma unroll
        for (int sc = 0; sc < 4; sc++) acc[sc * 16 + co] += bv;
    }
#pragma unroll
    for (int co = 0; co < 16; co++) {
        float* yp = y + (size_t)(n * 16 + co) * HH * WW + (size_t)oh * WW + ow0;
        float4 v0;
        v0.x = acc[0 * 16 + co]; v0.y = acc[1 * 16 + co];
        v0.z = acc[2 * 16 + co]; v0.w = acc[3 * 16 + co];
        *reinterpret_cast<float4*>(yp) = v0;
    }
    int lane = threadIdx.x & 31, wrp = threadIdx.x >> 5;
#pragma unroll
    for (int co = 0; co < 16; co++) {
        float s = 0.f, q = 0.f;
#pragma unroll
        for (int sc = 0; sc < 4; sc++) {
            float v = acc[sc * 16 + co];
            s += v;
            q += v * v;
        }
        for (int o = 16; o; o >>= 1) {
            s += __shfl_down_sync(0xffffffffu, s, o);
            q += __shfl_down_sync(0xffffffffu, q, o);
        }
        if (lane == 0) { ssm[wrp][co] = s; qsm[wrp][co] = q; }
    }
    __syncthreads();
    if (threadIdx.x < 16) {
        float s = 0.f, q = 0.f;
#pragma unroll
        for (int wpp = 0; wpp < 8; wpp++) { s += ssm[wpp][threadIdx.x]; q += qsm[wpp][threadIdx.x]; }
        int plane = n * 16 + threadIdx.x;
        g_ps[(size_t)plane * MAXB + blockIdx.x] = make_float2(s, q);
    }
}

// ---------------------------------------------------------------------------
// conv9: 7x7, 16->3 over PRE-NORMALIZED REFLECT-PADDED input (P=3), tanh out.
// Pure flat loads + FMA; no reflect math, no norm math, no predicates.
// ---------------------------------------------------------------------------
__global__ void __launch_bounds__(256) conv7_last(const float* __restrict__ xpad,
                                                  const float* __restrict__ w,
                                                  const float* __restrict__ bias,
                                                  float* __restrict__ y) {
    constexpr int WP = WW + 6;               // 518
    constexpr int PS = (HH + 6) * WP;        // 518*518
    __shared__ float wsm[16 * 49 * 3];
    for (int i = threadIdx.x; i < 16 * 49 * 3; i += 256) {
        int ci = i / (49 * 3);
        int rem = i - ci * (49 * 3);
        int tap = rem / 3;
        int co = rem - tap * 3;
        wsm[i] = w[(co * 16 + ci) * 49 + tap];
    }
    __syncthreads();

    int t = blockIdx.x * 256 + threadIdx.x;
    int n = blockIdx.y;
    int oh = t >> 6;
    int ow0 = (t & 63) * 8;

    float acc[8 * 3];
#pragma unroll
    for (int i = 0; i < 8 * 3; i++) acc[i] = 0.f;

    const float* xbase = xpad + (size_t)n * 16 * PS + (size_t)oh * WP + ow0;

#pragma unroll 1
    for (int ci = 0; ci < 16; ci++) {
        const float* xp = xbase + (size_t)ci * PS;
#pragma unroll 1
        for (int kh = 0; kh < 7; kh++) {
            const float* xr = xp + kh * WP;
            float xv[14];
#pragma unroll
            for (int c = 0; c < 14; c++) xv[c] = xr[c];
            const float* wb = wsm + (ci * 49 + kh * 7) * 3;
#pragma unroll
            for (int kw = 0; kw < 7; kw++) {
#pragma unroll
                for (int co = 0; co < 3; co++) {
                    float wvv = wb[kw * 3 + co];
#pragma unroll
                    for (int sc = 0; sc < 8; sc++)
                        acc[sc * 3 + co] = fmaf(xv[sc + kw], wvv, acc[sc * 3 + co]);
                }
            }
        }
    }
#pragma unroll
    for (int co = 0; co < 3; co++) {
        float bv = bias[co];
        float* yp = y + (size_t)(n * 3 + co) * HH * WW + (size_t)oh * WW + ow0;
        float4 v0, v1;
        v0.x = tanhf(acc[0 * 3 + co] + bv); v0.y = tanhf(acc[1 * 3 + co] + bv);
        v0.z = tanhf(acc[2 * 3 + co] + bv); v0.w = tanhf(acc[3 * 3 + co] + bv);
        v1.x = tanhf(acc[4 * 3 + co] + bv); v1.y = tanhf(acc[5 * 3 + co] + bv);
        v1.z = tanhf(acc[6 * 3 + co] + bv); v1.w = tanhf(acc[7 * 3 + co] + bv);
        ((float4*)yp)[0] = v0;
        ((float4*)yp)[1] = v1;
    }
}

// ---------------------------------------------------------------------------
// Segment mean: (label, slice) partials, deterministic, then combine.
// ---------------------------------------------------------------------------
__global__ void segpart_k(const float* __restrict__ feats, const int* __restrict__ inst) {
    int lab = blockIdx.x, slice = blockIdx.y;
    const int HWp = HH * WW;
    const int per = BB * HWp / 8;
    int start = slice * per;
    float c0 = 0.f, c1 = 0.f, c2 = 0.f, cnt = 0.f;
    for (int p = start + threadIdx.x; p < start + per; p += 256) {
        if (inst[p] == lab) {
            int n = p / HWp;
            int hw = p - n * HWp;
            const float* f = feats + (size_t)n * 3 * HWp + hw;
            c0 += f[0];
            c1 += f[HWp];
            c2 += f[2 * HWp];
            cnt += 1.f;
        }
    }
    __shared__ float s0[256], s1[256], s2[256], sc[256];
    s0[threadIdx.x] = c0; s1[threadIdx.x] = c1; s2[threadIdx.x] = c2; sc[threadIdx.x] = cnt;
    __syncthreads();
    for (int o = 128; o > 0; o >>= 1) {
        if (threadIdx.x < o) {
            s0[threadIdx.x] += s0[threadIdx.x + o];
            s1[threadIdx.x] += s1[threadIdx.x + o];
            s2[threadIdx.x] += s2[threadIdx.x + o];
            sc[threadIdx.x] += sc[threadIdx.x + o];
        }
        __syncthreads();
    }
    if (threadIdx.x == 0) {
        float* q = &g_part[(lab * 8 + slice) * 4];
        q[0] = s0[0]; q[1] = s1[0]; q[2] = s2[0]; q[3] = sc[0];
    }
}

__global__ void segfin_k() {
    int lab = threadIdx.x;
    if (lab >= NUM_INST) return;
    float s0 = 0.f, s1 = 0.f, s2 = 0.f, c = 0.f;
    for (int sl = 0; sl < 8; sl++) {
        const float* p = &g_part[(lab * 8 + sl) * 4];
        s0 += p[0]; s1 += p[1]; s2 += p[2]; c += p[3];
    }
    float d = fmaxf(c, 1.f);
    g_means[lab * 3 + 0] = s0 / d;
    g_means[lab * 3 + 1] = s1 / d;
    g_means[lab * 3 + 2] = s2 / d;
}

__global__ void gather_k(const int* __restrict__ inst, float* __restrict__ out) {
    int idx = blockIdx.x * 256 + threadIdx.x;
    const int Q = HH * WW / 4;
    if (idx >= BB * Q) return;
    int n = idx / Q, h4 = idx - n * Q;
    int4 lb = ((const int4*)inst)[(size_t)n * Q + h4];
#pragma unroll
    for (int c = 0; c < 3; c++) {
        float4 v;
        v.x = g_means[lb.x * 3 + c];
        v.y = g_means[lb.y * 3 + c];
        v.z = g_means[lb.z * 3 + c];
        v.w = g_means[lb.w * 3 + c];
        ((float4*)out)[(size_t)(n * 3 + c) * Q + h4] = v;
    }
}

// ---------------------------------------------------------------------------
extern "C" void kernel_launch(void* const* d_in, const int* in_sizes, int n_in,
                              void* d_out, int out_size) {
    const float* input = (const float*)d_in[0];
    const int* inst = (const int*)d_in[1];
    const float* w0 = (const float*)d_in[2];  const float* b0 = (const float*)d_in[3];
    const float* w1 = (const float*)d_in[4];  const float* b1 = (const float*)d_in[5];
    const float* w2 = (const float*)d_in[6];  const float* b2 = (const float*)d_in[7];
    const float* w3 = (const float*)d_in[8];  const float* b3 = (const float*)d_in[9];
    const float* w4 = (const float*)d_in[10]; const float* b4 = (const float*)d_in[11];
    const float* w5 = (const float*)d_in[12]; const float* b5 = (const float*)d_in[13];
    const float* w6 = (const float*)d_in[14]; const float* b6 = (const float*)d_in[15];
    const float* w7 = (const float*)d_in[16]; const float* b7 = (const float*)d_in[17];
    const float* w8 = (const float*)d_in[18]; const float* b8 = (const float*)d_in[19];
    const float* w9 = (const float*)d_in[20]; const float* b9 = (const float*)d_in[21];
    float* out = (float*)d_out;

    float* bufA; float* bufB; float* bufP;
    cudaGetSymbolAddress((void**)&bufA, g_bufA);
    cudaGetSymbolAddress((void**)&bufB, g_bufB);
    cudaGetSymbolAddress((void**)&bufP, g_bufP);

    const float i512 = 1.f / (512.f * 512.f);
    const float i256 = 1.f / (256.f * 256.f);
    const float i128 = 1.f / (128.f * 128.f);
    const float i64  = 1.f / (64.f * 64.f);
    const float i32  = 1.f / (32.f * 32.f);

    // conv0: raw input -> bufA [4,16,512,512], 256 stats partials/plane
    conv7_first<<<dim3(256, BB), 256>>>(input, w0, b0, bufA);
    normpad_k<<<dim3(514, BB * 16), 256>>>(bufA, bufP, 512, 512, 1, 0, 256, i512);

    conv_s2_t<16, 32, 8, 512, 512, 256><<<dim3(64, BB * 4), 256>>>(bufP, w1, b1, bufB);
    normpad_k<<<dim3(258, BB * 32), 256>>>(bufB, bufP, 256, 256, 1, 0, 64, i256);

    conv_s2_t<32, 64, 8, 256, 256, 256><<<dim3(16, BB * 8), 256>>>(bufP, w2, b2, bufA);
    normpad_k<<<dim3(130, BB * 64), 128>>>(bufA, bufP, 128, 128, 1, 0, 16, i128);

    conv_s2_t<64, 128, 4, 128, 128, 256><<<dim3(4, BB * 32), 256>>>(bufP, w3, b3, bufB);
    normpad_k<<<dim3(66, BB * 128), 64>>>(bufB, bufP, 64, 64, 1, 0, 4, i64);

    conv_s2_t<128, 256, 4, 64, 64, 256><<<dim3(1, BB * 64), 256>>>(bufP, w4, b4, bufA);
    normpad_k<<<dim3(34, BB * 256), 64>>>(bufA, bufP, 32, 32, 1, 0, 1, i32);

    deconv_t<256, 128, 4, 2, 32, 32, 256><<<dim3(4, BB * 32), 256>>>(bufP, w5, b5, bufB);
    normpad_k<<<dim3(66, BB * 128), 64>>>(bufB, bufP, 64, 64, 1, 0, 4, i64);

    deconv_t<128, 64, 8, 2, 64, 64, 256><<<dim3(16, BB * 8), 256>>>(bufP, w6, b6, bufA);
    normpad_k<<<dim3(130, BB * 64), 128>>>(bufA, bufP, 128, 128, 1, 0, 16, i128);

    deconv_t<64, 32, 8, 2, 128, 128, 256><<<dim3(64, BB * 4), 256>>>(bufP, w7, b7, bufB);
    normpad_k<<<dim3(258, BB * 32), 256>>>(bufB, bufP, 256, 256, 1, 0, 64, i256);

    deconv_t<32, 16, 8, 2, 256, 256, 256><<<dim3(256, BB * 2), 256>>>(bufP, w8, b8, bufA);
    // reflect-pad P=3 normalized input for conv9
    normpad_k<<<dim3(518, BB * 16), 256>>>(bufA, bufP, 512, 512, 3, 1, 256, i512);

    // conv9 + tanh: bufP -> bufB [4,3,512,512]
    conv7_last<<<dim3(128, BB), 256>>>(bufP, w9, b9, bufB);

    // segment mean + gather
    segpart_k<<<dim3(NUM_INST, 8), 256>>>(bufB, inst);
    segfin_k<<<1, 32>>>();
    gather_k<<<(BB * HH * WW / 4 + 255) / 256, 256>>>(inst, out);
}

// round 15
// speedup vs baseline: 1.0700x; 1.0700x over previous
#include <cuda_runtime.h>
#include <math.h>

#define BB 4
#define HH 512
#define WW 512
#define NUM_INST 32
#define EPS 1e-5f
#define MAXB 256

// Raw ping-pong activation buffers (max 4*16*512*512 floats = 64MB each)
__device__ float g_bufA[BB * 16 * HH * WW];
__device__ float g_bufB[BB * 16 * HH * WW];
// Normalized + padded input buffer (max 4*16*518*520 floats ~ 69MB)
__device__ float g_bufP[BB * 16 * 520 * 520];
// Per-(plane,block) stats partials (sum, sumsq)
__device__ float2 g_ps[BB * 256 * MAXB];
__device__ float g_means[NUM_INST * 3];
__device__ float g_part[NUM_INST * 8 * 4];

__device__ __forceinline__ int refl(int i, int n) {
    return i < 0 ? -i : (i >= n ? 2 * n - 2 - i : i);
}

// ---------------------------------------------------------------------------
// normpad: finalize per-plane stats from partials, write relu((x-m)*rs) into
// a padded plane. Layout: Wp = W + 8, unpadded col c at offset 4+c (aligned
// float4 interior); rows: unpadded row h at row P+h, Hp = H + 2P.
// Border P: zeros (reflect=0) or reflect (reflect=1). Bandwidth-bound.
// ---------------------------------------------------------------------------
__global__ void normpad_k(const float* __restrict__ y, float* __restrict__ xp,
                          int H, int W, int P, int reflect, int nblk, float invHW) {
    int plane = blockIdx.y;
    int Hp = H + 2 * P, Wp = W + 8;
    __shared__ float smv[2];
    if (threadIdx.x < 32) {
        float s = 0.f, q = 0.f;
        const float2* pp = g_ps + (size_t)plane * MAXB;
        for (int i = threadIdx.x; i < nblk; i += 32) {
            float2 v = pp[i];
            s += v.x;
            q += v.y;
        }
        for (int o = 16; o; o >>= 1) {
            s += __shfl_down_sync(0xffffffffu, s, o);
            q += __shfl_down_sync(0xffffffffu, q, o);
        }
        if (threadIdx.x == 0) {
            float m = s * invHW;
            float var = q * invHW - m * m;
            smv[0] = m;
            smv[1] = rsqrtf(var + EPS);
        }
    }
    __syncthreads();
    float m = smv[0], rs = smv[1];
    float nb = -m * rs;
    const float* ypl = y + (size_t)plane * H * W;
    float* xpl = xp + (size_t)plane * Hp * Wp;

    for (int hp = blockIdx.x; hp < Hp; hp += gridDim.x) {
        int h = hp - P;
        bool hv = true;
        if (reflect) h = refl(h, H);
        else hv = (unsigned)h < (unsigned)H;
        float* orow = xpl + (size_t)hp * Wp;
        if (!hv) {
            float4 z = make_float4(0.f, 0.f, 0.f, 0.f);
            for (int i = threadIdx.x; i < Wp / 4; i += blockDim.x)
                reinterpret_cast<float4*>(orow)[i] = z;
            continue;
        }
        const float* row = ypl + (size_t)h * W;
        // interior: aligned float4 in, aligned float4 out at offset 4
        for (int i = threadIdx.x; i < W / 4; i += blockDim.x) {
            float4 v = reinterpret_cast<const float4*>(row)[i];
            v.x = fmaxf(fmaf(v.x, rs, nb), 0.f);
            v.y = fmaxf(fmaf(v.y, rs, nb), 0.f);
            v.z = fmaxf(fmaf(v.z, rs, nb), 0.f);
            v.w = fmaxf(fmaf(v.w, rs, nb), 0.f);
            reinterpret_cast<float4*>(orow + 4)[i] = v;
        }
        // borders: 8 scalar slots (pcol 0..3 and 4+W..Wp-1)
        if (threadIdx.x < 8) {
            int pc = (threadIdx.x < 4) ? (int)threadIdx.x : (4 + W + (int)threadIdx.x - 4);
            int c = pc - 4;
            float val = 0.f;
            if (reflect && c >= -P && c < W + P) {
                float raw = row[refl(c, W)];
                val = fmaxf(fmaf(raw, rs, nb), 0.f);
            }
            orow[pc] = val;
        }
    }
}

// ---------------------------------------------------------------------------
// 3x3 stride-2 conv over PRE-NORMALIZED PADDED input (pad=1, layout above).
// Thread = 2x2 outputs x COPT channels. Flat inner loop: 25 plain LDG off one
// base pointer + 9*V LDS.128 + 36*COPT FMA, no predicates, no norm math.
// Fused stats partials on OUTPUT into g_ps.
// ---------------------------------------------------------------------------
template <int CIN, int COUT, int COPT, int HIN, int WIN, int NT>
__global__ void __launch_bounds__(NT) conv_s2_t(const float* __restrict__ xpad,
                                                const float* __restrict__ w,
                                                const float* __restrict__ bias,
                                                float* __restrict__ y) {
    constexpr int HOUT = HIN / 2, WOUT = WIN / 2;
    constexpr int TW = WOUT / 2;
    constexpr int WP = WIN + 8;
    constexpr int PS = (HIN + 2) * WP;
    constexpr int CHUNK = (CIN < 64) ? CIN : 64;
    constexpr int V = COPT / 4;
    __shared__ __align__(16) float wsm[CHUNK * 9 * COPT];
    __shared__ float ssm[NT / 32][COPT], qsm[NT / 32][COPT];

    int t = blockIdx.x * NT + threadIdx.x;
    int cog = blockIdx.y % (COUT / COPT);
    int n = blockIdx.y / (COUT / COPT);
    int oh0 = (t / TW) * 2, ow0 = (t % TW) * 2;
    int lane = threadIdx.x & 31, wrp = threadIdx.x >> 5;

    float acc[4 * COPT];
#pragma unroll
    for (int i = 0; i < 4 * COPT; i++) acc[i] = 0.f;

    const float* xbase = xpad + (size_t)n * CIN * PS + (size_t)(oh0 * 2) * WP + ow0 * 2 + 3;

#pragma unroll 1
    for (int c0 = 0; c0 < CIN; c0 += CHUNK) {
        __syncthreads();
        for (int i = threadIdx.x; i < CHUNK * 9 * COPT; i += NT) {
            int ci_l = i / (9 * COPT);
            int rem = i - ci_l * (9 * COPT);
            int tap = rem / COPT;
            int u = rem - tap * COPT;
            wsm[i] = w[((size_t)(cog * COPT + u) * CIN + c0 + ci_l) * 9 + tap];
        }
        __syncthreads();
#pragma unroll 1
        for (int ci_l = 0; ci_l < CHUNK; ci_l++) {
            const float* xp = xbase + (size_t)(c0 + ci_l) * PS;

            float xv[25];
#pragma unroll
            for (int r = 0; r < 5; r++)
#pragma unroll
                for (int c = 0; c < 5; c++)
                    xv[r * 5 + c] = xp[r * WP + c];

            const float4* wp4 = reinterpret_cast<const float4*>(wsm + ci_l * 9 * COPT);
#pragma unroll
            for (int kh = 0; kh < 3; kh++) {
#pragma unroll
                for (int kw = 0; kw < 3; kw++) {
#pragma unroll
                    for (int v = 0; v < V; v++) {
                        float4 wq = wp4[(kh * 3 + kw) * V + v];
                        float wa[4] = {wq.x, wq.y, wq.z, wq.w};
#pragma unroll
                        for (int j = 0; j < 4; j++) {
#pragma unroll
                            for (int orow = 0; orow < 2; orow++)
#pragma unroll
                                for (int oc = 0; oc < 2; oc++)
                                    acc[(orow * 2 + oc) * COPT + v * 4 + j] =
                                        fmaf(xv[(2 * orow + kh) * 5 + 2 * oc + kw], wa[j],
                                             acc[(orow * 2 + oc) * COPT + v * 4 + j]);
                        }
                    }
                }
            }
        }
    }
#pragma unroll
    for (int u = 0; u < COPT; u++) {
        float bv = bias[cog * COPT + u];
#pragma unroll
        for (int p = 0; p < 4; p++) acc[p * COPT + u] += bv;
    }
    size_t obase = (size_t)(n * COUT + cog * COPT) * HOUT * WOUT + (size_t)oh0 * WOUT + ow0;
#pragma unroll
    for (int u = 0; u < COPT; u++) {
#pragma unroll
        for (int orow = 0; orow < 2; orow++) {
            float* yp = y + obase + (size_t)u * HOUT * WOUT + (size_t)orow * WOUT;
            float2 v;
            v.x = acc[(orow * 2 + 0) * COPT + u];
            v.y = acc[(orow * 2 + 1) * COPT + u];
            *reinterpret_cast<float2*>(yp) = v;
        }
    }
#pragma unroll
    for (int u = 0; u < COPT; u++) {
        float s = 0.f, q = 0.f;
#pragma unroll
        for (int p = 0; p < 4; p++) {
            float v = acc[p * COPT + u];
            s += v;
            q += v * v;
        }
        for (int o = 16; o; o >>= 1) {
            s += __shfl_down_sync(0xffffffffu, s, o);
            q += __shfl_down_sync(0xffffffffu, q, o);
        }
        if (lane == 0) { ssm[wrp][u] = s; qsm[wrp][u] = q; }
    }
    __syncthreads();
    if (threadIdx.x < COPT) {
        float s = 0.f, q = 0.f;
#pragma unroll
        for (int wpp = 0; wpp < NT / 32; wpp++) { s += ssm[wpp][threadIdx.x]; q += qsm[wpp][threadIdx.x]; }
        int plane = n * COUT + cog * COPT + threadIdx.x;
        g_ps[(size_t)plane * MAXB + blockIdx.x] = make_float2(s, q);
    }
}

// ---------------------------------------------------------------------------
// ConvTranspose2d k=3 s=2 p=1 op=1 over PRE-NORMALIZED PADDED input (pad=1).
// TS x TS tile, weight layout (CIN, COUT, 3, 3). No predicates, no norm math.
// ---------------------------------------------------------------------------
template <int CIN, int COUT, int COPT, int TS, int HIN, int WIN, int NT>
__global__ void __launch_bounds__(NT) deconv_t(const float* __restrict__ xpad,
                                               const float* __restrict__ w,
                                               const float* __restrict__ bias,
                                               float* __restrict__ y) {
    constexpr int HOUT = HIN * 2, WOUT = WIN * 2;
    constexpr int TW = WOUT / TS;
    constexpr int SUB = TS / 2;
    constexpr int WP = WIN + 8;
    constexpr int PS = (HIN + 2) * WP;
    constexpr int CHUNK = (CIN < 64) ? CIN : 64;
    constexpr int V = COPT / 4;
    __shared__ __align__(16) float wsm[CHUNK * 9 * COPT];
    __shared__ float ssm[NT / 32][COPT], qsm[NT / 32][COPT];

    int t = blockIdx.x * NT + threadIdx.x;
    int cog = blockIdx.y % (COUT / COPT);
    int n = blockIdx.y / (COUT / COPT);
    int oh0 = (t / TW) * TS, ow0 = (t % TW) * TS;
    int i0 = oh0 >> 1, j0 = ow0 >> 1;
    int lane = threadIdx.x & 31, wrp = threadIdx.x >> 5;

    float acc[TS * TS * COPT];
#pragma unroll
    for (int i = 0; i < TS * TS * COPT; i++) acc[i] = 0.f;

    const float* xbase = xpad + (size_t)n * CIN * PS + (size_t)(i0 + 1) * WP + j0 + 4;

#pragma unroll 1
    for (int c0 = 0; c0 < CIN; c0 += CHUNK) {
        __syncthreads();
        for (int i = threadIdx.x; i < CHUNK * 9 * COPT; i += NT) {
            int ci_l = i / (9 * COPT);
            int rem = i - ci_l * (9 * COPT);
            int tap = rem / COPT;
            int u = rem - tap * COPT;
            wsm[i] = w[((size_t)(c0 + ci_l) * COUT + cog * COPT + u) * 9 + tap];
        }
        __syncthreads();
#pragma unroll 1
        for (int ci_l = 0; ci_l < CHUNK; ci_l++) {
            const float* xp = xbase + (size_t)(c0 + ci_l) * PS;
            float xr[(SUB + 1) * (SUB + 1)];
#pragma unroll
            for (int r = 0; r <= SUB; r++)
#pragma unroll
                for (int c = 0; c <= SUB; c++)
                    xr[r * (SUB + 1) + c] = xp[r * WP + c];

#pragma unroll
            for (int kh = 0; kh < 3; kh++) {
                int orl = (kh == 1) ? 0 : 1;
                int xro = (kh == 0) ? 1 : 0;
#pragma unroll
                for (int kw = 0; kw < 3; kw++) {
                    int ocl = (kw == 1) ? 0 : 1;
                    int xco = (kw == 0) ? 1 : 0;
                    const float4* wp4 =
                        reinterpret_cast<const float4*>(wsm + (ci_l * 9 + kh * 3 + kw) * COPT);
#pragma unroll
                    for (int v = 0; v < V; v++) {
                        float4 wq = wp4[v];
                        float wa[4] = {wq.x, wq.y, wq.z, wq.w};
#pragma unroll
                        for (int j = 0; j < 4; j++) {
#pragma unroll
                            for (int a = 0; a < SUB; a++)
#pragma unroll
                                for (int b = 0; b < SUB; b++)
                                    acc[((2 * a + orl) * TS + (2 * b + ocl)) * COPT + v * 4 + j] =
                                        fmaf(xr[(a + xro) * (SUB + 1) + (b + xco)], wa[j],
                                             acc[((2 * a + orl) * TS + (2 * b + ocl)) * COPT + v * 4 + j]);
                        }
                    }
                }
            }
        }
    }
#pragma unroll
    for (int u = 0; u < COPT; u++) {
        float bv = bias[cog * COPT + u];
#pragma unroll
        for (int p = 0; p < TS * TS; p++) acc[p * COPT + u] += bv;
    }
    size_t obase = (size_t)(n * COUT + cog * COPT) * HOUT * WOUT + (size_t)oh0 * WOUT + ow0;
#pragma unroll
    for (int u = 0; u < COPT; u++) {
#pragma unroll
        for (int orow = 0; orow < TS; orow++) {
            float* yp = y + obase + (size_t)u * HOUT * WOUT + (size_t)orow * WOUT;
            float2 v;
            v.x = acc[(orow * TS + 0) * COPT + u];
            v.y = acc[(orow * TS + 1) * COPT + u];
            *reinterpret_cast<float2*>(yp) = v;
        }
    }
#pragma unroll
    for (int u = 0; u < COPT; u++) {
        float s = 0.f, q = 0.f;
#pragma unroll
        for (int p = 0; p < TS * TS; p++) {
            float v = acc[p * COPT + u];
            s += v;
            q += v * v;
        }
        for (int o = 16; o; o >>= 1) {
            s += __shfl_down_sync(0xffffffffu, s, o);
            q += __shfl_down_sync(0xffffffffu, q, o);
        }
        if (lane == 0) { ssm[wrp][u] = s; qsm[wrp][u] = q; }
    }
    __syncthreads();
    if (threadIdx.x < COPT) {
        float s = 0.f, q = 0.f;
#pragma unroll
        for (int wpp = 0; wpp < NT / 32; wpp++) { s += ssm[wpp][threadIdx.x]; q += qsm[wpp][threadIdx.x]; }
        int plane = n * COUT + cog * COPT + threadIdx.x;
        g_ps[(size_t)plane * MAXB + blockIdx.x] = make_float2(s, q);
    }
}

// ---------------------------------------------------------------------------
// conv0: reflect-pad 3, 7x7, 3->16. Thread = 1 row x 4 cols, all 16 co.
// Reads raw global input (reflect handled inline; only 3 channels).
// ---------------------------------------------------------------------------
__global__ void __launch_bounds__(256) conv7_first(const float* __restrict__ x,
                                                   const float* __restrict__ w,
                                                   const float* __restrict__ bias,
                                                   float* __restrict__ y) {
    __shared__ __align__(16) float wsm[3 * 49 * 16];
    __shared__ float ssm[8][16], qsm[8][16];
    for (int i = threadIdx.x; i < 3 * 49 * 16; i += 256) {
        int ci = i / (49 * 16);
        int rem = i - ci * (49 * 16);
        int tap = rem / 16;
        int co = rem - tap * 16;
        wsm[i] = w[(co * 3 + ci) * 49 + tap];
    }
    __syncthreads();

    int t = blockIdx.x * 256 + threadIdx.x;
    int n = blockIdx.y;
    int oh = t >> 7;
    int ow0 = (t & 127) * 4;

    int iwI[10];
#pragma unroll
    for (int c = 0; c < 10; c++) iwI[c] = refl(ow0 - 3 + c, WW);
    bool wInt = (ow0 >= 4) && (ow0 + 7 <= WW - 1);

    float acc[4 * 16];
#pragma unroll
    for (int i = 0; i < 4 * 16; i++) acc[i] = 0.f;

#pragma unroll 1
    for (int ci = 0; ci < 3; ci++) {
        const float* xp = x + (size_t)(n * 3 + ci) * HH * WW;
#pragma unroll 1
        for (int kh = 0; kh < 7; kh++) {
            const float* xr = xp + (size_t)refl(oh + kh - 3, HH) * WW;
            float xv[10];
            if (wInt) {
                const float* b = xr + ow0;
                float4 qa = *reinterpret_cast<const float4*>(b - 4);
                float4 qb = *reinterpret_cast<const float4*>(b);
                float4 qc = *reinterpret_cast<const float4*>(b + 4);
                xv[0] = qa.y; xv[1] = qa.z; xv[2] = qa.w;
                xv[3] = qb.x; xv[4] = qb.y; xv[5] = qb.z; xv[6] = qb.w;
                xv[7] = qc.x; xv[8] = qc.y; xv[9] = qc.z;
            } else {
#pragma unroll
                for (int c = 0; c < 10; c++) xv[c] = xr[iwI[c]];
            }
            const float4* wb4 = reinterpret_cast<const float4*>(wsm + (ci * 49 + kh * 7) * 16);
#pragma unroll
            for (int kw = 0; kw < 7; kw++) {
#pragma unroll
                for (int v = 0; v < 4; v++) {
                    float4 wq = wb4[kw * 4 + v];
                    float wa[4] = {wq.x, wq.y, wq.z, wq.w};
#pragma unroll
                    for (int j = 0; j < 4; j++) {
#pragma unroll
                        for (int sc = 0; sc < 4; sc++)
                            acc[sc * 16 + v * 4 + j] = fmaf(xv[sc + kw], wa[j], acc[sc * 16 + v * 4 + j]);
                    }
                }
            }
        }
    }
#pragma unroll
    for (int co = 0; co < 16; co++) {
        float bv = bias[co];
#pragma unroll
        for (int sc = 0; sc < 4; sc++) acc[sc * 16 + co] += bv;
    }
#pragma unroll
    for (int co = 0; co < 16; co++) {
        float* yp = y + (size_t)(n * 16 + co) * HH * WW + (size_t)oh * WW + ow0;
        float4 v0;
        v0.x = acc[0 * 16 + co]; v0.y = acc[1 * 16 + co];
        v0.z = acc[2 * 16 + co]; v0.w = acc[3 * 16 + co];
        *reinterpret_cast<float4*>(yp) = v0;
    }
    int lane = threadIdx.x & 31, wrp = threadIdx.x >> 5;
#pragma unroll
    for (int co = 0; co < 16; co++) {
        float s = 0.f, q = 0.f;
#pragma unroll
        for (int sc = 0; sc < 4; sc++) {
            float v = acc[sc * 16 + co];
            s += v;
            q += v * v;
        }
        for (int o = 16; o; o >>= 1) {
            s += __shfl_down_sync(0xffffffffu, s, o);
            q += __shfl_down_sync(0xffffffffu, q, o);
        }
        if (lane == 0) { ssm[wrp][co] = s; qsm[wrp][co] = q; }
    }
    __syncthreads();
    if (threadIdx.x < 16) {
        float s = 0.f, q = 0.f;
#pragma unroll
        for (int wpp = 0; wpp < 8; wpp++) { s += ssm[wpp][threadIdx.x]; q += qsm[wpp][threadIdx.x]; }
        int plane = n * 16 + threadIdx.x;
        g_ps[(size_t)plane * MAXB + blockIdx.x] = make_float2(s, q);
    }
}

// ---------------------------------------------------------------------------
// conv9: 7x7, 16->3 over PRE-NORMALIZED REFLECT-PADDED input (pad=3), tanh.
// Pure flat loads + FMA; no reflect math, no norm math, no predicates.
// ---------------------------------------------------------------------------
__global__ void __launch_bounds__(256) conv7_last(const float* __restrict__ xpad,
                                                  const float* __restrict__ w,
                                                  const float* __restrict__ bias,
                                                  float* __restrict__ y) {
    constexpr int WP = WW + 8;               // 520
    constexpr int PS = (HH + 6) * WP;        // 518*520
    __shared__ float wsm[16 * 49 * 3];
    for (int i = threadIdx.x; i < 16 * 49 * 3; i += 256) {
        int ci = i / (49 * 3);
        int rem = i - ci * (49 * 3);
        int tap = rem / 3;
        int co = rem - tap * 3;
        wsm[i] = w[(co * 16 + ci) * 49 + tap];
    }
    __syncthreads();

    int t = blockIdx.x * 256 + threadIdx.x;
    int n = blockIdx.y;
    int oh = t >> 6;
    int ow0 = (t & 63) * 8;

    float acc[8 * 3];
#pragma unroll
    for (int i = 0; i < 8 * 3; i++) acc[i] = 0.f;

    const float* xbase = xpad + (size_t)n * 16 * PS + (size_t)oh * WP + ow0 + 1;

#pragma unroll 1
    for (int ci = 0; ci < 16; ci++) {
        const float* xp = xbase + (size_t)ci * PS;
#pragma unroll 1
        for (int kh = 0; kh < 7; kh++) {
            const float* xr = xp + kh * WP;
            float xv[14];
#pragma unroll
            for (int c = 0; c < 14; c++) xv[c] = xr[c];
            const float* wb = wsm + (ci * 49 + kh * 7) * 3;
#pragma unroll
            for (int kw = 0; kw < 7; kw++) {
#pragma unroll
                for (int co = 0; co < 3; co++) {
                    float wvv = wb[kw * 3 + co];
#pragma unroll
                    for (int sc = 0; sc < 8; sc++)
                        acc[sc * 3 + co] = fmaf(xv[sc + kw], wvv, acc[sc * 3 + co]);
                }
            }
        }
    }
#pragma unroll
    for (int co = 0; co < 3; co++) {
        float bv = bias[co];
        float* yp = y + (size_t)(n * 3 + co) * HH * WW + (size_t)oh * WW + ow0;
        float4 v0, v1;
        v0.x = tanhf(acc[0 * 3 + co] + bv); v0.y = tanhf(acc[1 * 3 + co] + bv);
        v0.z = tanhf(acc[2 * 3 + co] + bv); v0.w = tanhf(acc[3 * 3 + co] + bv);
        v1.x = tanhf(acc[4 * 3 + co] + bv); v1.y = tanhf(acc[5 * 3 + co] + bv);
        v1.z = tanhf(acc[6 * 3 + co] + bv); v1.w = tanhf(acc[7 * 3 + co] + bv);
        ((float4*)yp)[0] = v0;
        ((float4*)yp)[1] = v1;
    }
}

// ---------------------------------------------------------------------------
// Segment mean: (label, slice) partials, deterministic, then combine.
// ---------------------------------------------------------------------------
__global__ void segpart_k(const float* __restrict__ feats, const int* __restrict__ inst) {
    int lab = blockIdx.x, slice = blockIdx.y;
    const int HWp = HH * WW;
    const int per = BB * HWp / 8;
    int start = slice * per;
    float c0 = 0.f, c1 = 0.f, c2 = 0.f, cnt = 0.f;
    for (int p = start + threadIdx.x; p < start + per; p += 256) {
        if (inst[p] == lab) {
            int n = p / HWp;
            int hw = p - n * HWp;
            const float* f = feats + (size_t)n * 3 * HWp + hw;
            c0 += f[0];
            c1 += f[HWp];
            c2 += f[2 * HWp];
            cnt += 1.f;
        }
    }
    __shared__ float s0[256], s1[256], s2[256], sc[256];
    s0[threadIdx.x] = c0; s1[threadIdx.x] = c1; s2[threadIdx.x] = c2; sc[threadIdx.x] = cnt;
    __syncthreads();
    for (int o = 128; o > 0; o >>= 1) {
        if (threadIdx.x < o) {
            s0[threadIdx.x] += s0[threadIdx.x + o];
            s1[threadIdx.x] += s1[threadIdx.x + o];
            s2[threadIdx.x] += s2[threadIdx.x + o];
            sc[threadIdx.x] += sc[threadIdx.x + o];
        }
        __syncthreads();
    }
    if (threadIdx.x == 0) {
        float* q = &g_part[(lab * 8 + slice) * 4];
        q[0] = s0[0]; q[1] = s1[0]; q[2] = s2[0]; q[3] = sc[0];
    }
}

__global__ void segfin_k() {
    int lab = threadIdx.x;
    if (lab >= NUM_INST) return;
    float s0 = 0.f, s1 = 0.f, s2 = 0.f, c = 0.f;
    for (int sl = 0; sl < 8; sl++) {
        const float* p = &g_part[(lab * 8 + sl) * 4];
        s0 += p[0]; s1 += p[1]; s2 += p[2]; c += p[3];
    }
    float d = fmaxf(c, 1.f);
    g_means[lab * 3 + 0] = s0 / d;
    g_means[lab * 3 + 1] = s1 / d;
    g_means[lab * 3 + 2] = s2 / d;
}

__global__ void gather_k(const int* __restrict__ inst, float* __restrict__ out) {
    int idx = blockIdx.x * 256 + threadIdx.x;
    const int Q = HH * WW / 4;
    if (idx >= BB * Q) return;
    int n = idx / Q, h4 = idx - n * Q;
    int4 lb = ((const int4*)inst)[(size_t)n * Q + h4];
#pragma unroll
    for (int c = 0; c < 3; c++) {
        float4 v;
        v.x = g_means[lb.x * 3 + c];
        v.y = g_means[lb.y * 3 + c];
        v.z = g_means[lb.z * 3 + c];
        v.w = g_means[lb.w * 3 + c];
        ((float4*)out)[(size_t)(n * 3 + c) * Q + h4] = v;
    }
}

// ---------------------------------------------------------------------------
extern "C" void kernel_launch(void* const* d_in, const int* in_sizes, int n_in,
                              void* d_out, int out_size) {
    const float* input = (const float*)d_in[0];
    const int* inst = (const int*)d_in[1];
    const float* w0 = (const float*)d_in[2];  const float* b0 = (const float*)d_in[3];
    const float* w1 = (const float*)d_in[4];  const float* b1 = (const float*)d_in[5];
    const float* w2 = (const float*)d_in[6];  const float* b2 = (const float*)d_in[7];
    const float* w3 = (const float*)d_in[8];  const float* b3 = (const float*)d_in[9];
    const float* w4 = (const float*)d_in[10]; const float* b4 = (const float*)d_in[11];
    const float* w5 = (const float*)d_in[12]; const float* b5 = (const float*)d_in[13];
    const float* w6 = (const float*)d_in[14]; const float* b6 = (const float*)d_in[15];
    const float* w7 = (const float*)d_in[16]; const float* b7 = (const float*)d_in[17];
    const float* w8 = (const float*)d_in[18]; const float* b8 = (const float*)d_in[19];
    const float* w9 = (const float*)d_in[20]; const float* b9 = (const float*)d_in[21];
    float* out = (float*)d_out;

    float* bufA; float* bufB; float* bufP;
    cudaGetSymbolAddress((void**)&bufA, g_bufA);
    cudaGetSymbolAddress((void**)&bufB, g_bufB);
    cudaGetSymbolAddress((void**)&bufP, g_bufP);

    const float i512 = 1.f / (512.f * 512.f);
    const float i256 = 1.f / (256.f * 256.f);
    const float i128 = 1.f / (128.f * 128.f);
    const float i64  = 1.f / (64.f * 64.f);
    const float i32  = 1.f / (32.f * 32.f);

    // conv0: raw input -> bufA [4,16,512,512], 256 stats partials/plane
    conv7_first<<<dim3(256, BB), 256>>>(input, w0, b0, bufA);
    normpad_k<<<dim3(514, BB * 16), 128>>>(bufA, bufP, 512, 512, 1, 0, 256, i512);

    conv_s2_t<16, 32, 8, 512, 512, 256><<<dim3(64, BB * 4), 256>>>(bufP, w1, b1, bufB);
    normpad_k<<<dim3(258, BB * 32), 64>>>(bufB, bufP, 256, 256, 1, 0, 64, i256);

    conv_s2_t<32, 64, 8, 256, 256, 256><<<dim3(16, BB * 8), 256>>>(bufP, w2, b2, bufA);
    normpad_k<<<dim3(130, BB * 64), 32>>>(bufA, bufP, 128, 128, 1, 0, 16, i128);

    conv_s2_t<64, 128, 4, 128, 128, 256><<<dim3(4, BB * 32), 256>>>(bufP, w3, b3, bufB);
    normpad_k<<<dim3(66, BB * 128), 32>>>(bufB, bufP, 64, 64, 1, 0, 4, i64);

    conv_s2_t<128, 256, 4, 64, 64, 256><<<dim3(1, BB * 64), 256>>>(bufP, w4, b4, bufA);
    normpad_k<<<dim3(34, BB * 256), 32>>>(bufA, bufP, 32, 32, 1, 0, 1, i32);

    deconv_t<256, 128, 4, 2, 32, 32, 256><<<dim3(4, BB * 32), 256>>>(bufP, w5, b5, bufB);
    normpad_k<<<dim3(66, BB * 128), 32>>>(bufB, bufP, 64, 64, 1, 0, 4, i64);

    deconv_t<128, 64, 8, 2, 64, 64, 256><<<dim3(16, BB * 8), 256>>>(bufP, w6, b6, bufA);
    normpad_k<<<dim3(130, BB * 64), 32>>>(bufA, bufP, 128, 128, 1, 0, 16, i128);

    deconv_t<64, 32, 8, 2, 128, 128, 256><<<dim3(64, BB * 4), 256>>>(bufP, w7, b7, bufB);
    normpad_k<<<dim3(258, BB * 32), 64>>>(bufB, bufP, 256, 256, 1, 0, 64, i256);

    deconv_t<32, 16, 8, 2, 256, 256, 256><<<dim3(256, BB * 2), 256>>>(bufP, w8, b8, bufA);
    // reflect-pad P=3 normalized input for conv9
    normpad_k<<<dim3(518, BB * 16), 128>>>(bufA, bufP, 512, 512, 3, 1, 256, i512);

    // conv9 + tanh: bufP -> bufB [4,3,512,512]
    conv7_last<<<dim3(128, BB), 256>>>(bufP, w9, b9, bufB);

    // segment mean + gather
    segpart_k<<<dim3(NUM_INST, 8), 256>>>(bufB, inst);
    segfin_k<<<1, 32>>>();
    gather_k<<<(BB * HH * WW / 4 + 255) / 256, 256>>>(inst, out);
}

// round 16
// speedup vs baseline: 1.2240x; 1.1439x over previous
#include <cuda_runtime.h>
#include <math.h>

#define BB 4
#define HH 512
#define WW 512
#define NUM_INST 32
#define EPS 1e-5f
#define MAXB 256

// Raw ping-pong activation buffers (max 4*16*512*512 floats = 64MB each)
__device__ float g_bufA[BB * 16 * HH * WW];
__device__ float g_bufB[BB * 16 * HH * WW];
// Normalized + padded input buffer (max 4*16*518*520 floats ~ 69MB)
__device__ float g_bufP[BB * 16 * 520 * 520];
// Per-(plane,block) stats partials (sum, sumsq)
__device__ float2 g_ps[BB * 256 * MAXB];
__device__ float g_means[NUM_INST * 3];
__device__ float g_part[NUM_INST * 8 * 4];

__device__ __forceinline__ int refl(int i, int n) {
    return i < 0 ? -i : (i >= n ? 2 * n - 2 - i : i);
}

// ---------------------------------------------------------------------------
// normpad: finalize per-plane stats from partials, write relu((x-m)*rs) into
// a padded plane. Layout: Wp = W + 8, unpadded col c at offset 4+c (aligned
// float4 interior); rows: unpadded row h at row P+h, Hp = H + 2P.
// Border P: zeros (reflect=0) or reflect (reflect=1). Bandwidth-bound.
// ---------------------------------------------------------------------------
__global__ void normpad_k(const float* __restrict__ y, float* __restrict__ xp,
                          int H, int W, int P, int reflect, int nblk, float invHW) {
    int plane = blockIdx.y;
    int Hp = H + 2 * P, Wp = W + 8;
    __shared__ float smv[2];
    if (threadIdx.x < 32) {
        float s = 0.f, q = 0.f;
        const float2* pp = g_ps + (size_t)plane * MAXB;
        for (int i = threadIdx.x; i < nblk; i += 32) {
            float2 v = pp[i];
            s += v.x;
            q += v.y;
        }
        for (int o = 16; o; o >>= 1) {
            s += __shfl_down_sync(0xffffffffu, s, o);
            q += __shfl_down_sync(0xffffffffu, q, o);
        }
        if (threadIdx.x == 0) {
            float m = s * invHW;
            float var = q * invHW - m * m;
            smv[0] = m;
            smv[1] = rsqrtf(var + EPS);
        }
    }
    __syncthreads();
    float m = smv[0], rs = smv[1];
    float nb = -m * rs;
    const float* ypl = y + (size_t)plane * H * W;
    float* xpl = xp + (size_t)plane * Hp * Wp;

    for (int hp = blockIdx.x; hp < Hp; hp += gridDim.x) {
        int h = hp - P;
        bool hv = true;
        if (reflect) h = refl(h, H);
        else hv = (unsigned)h < (unsigned)H;
        float* orow = xpl + (size_t)hp * Wp;
        if (!hv) {
            float4 z = make_float4(0.f, 0.f, 0.f, 0.f);
            for (int i = threadIdx.x; i < Wp / 4; i += blockDim.x)
                reinterpret_cast<float4*>(orow)[i] = z;
            continue;
        }
        const float* row = ypl + (size_t)h * W;
        for (int i = threadIdx.x; i < W / 4; i += blockDim.x) {
            float4 v = reinterpret_cast<const float4*>(row)[i];
            v.x = fmaxf(fmaf(v.x, rs, nb), 0.f);
            v.y = fmaxf(fmaf(v.y, rs, nb), 0.f);
            v.z = fmaxf(fmaf(v.z, rs, nb), 0.f);
            v.w = fmaxf(fmaf(v.w, rs, nb), 0.f);
            reinterpret_cast<float4*>(orow + 4)[i] = v;
        }
        if (threadIdx.x < 8) {
            int pc = (threadIdx.x < 4) ? (int)threadIdx.x : (4 + W + (int)threadIdx.x - 4);
            int c = pc - 4;
            float val = 0.f;
            if (reflect && c >= -P && c < W + P) {
                float raw = row[refl(c, W)];
                val = fmaxf(fmaf(raw, rs, nb), 0.f);
            }
            orow[pc] = val;
        }
    }
}

// ---------------------------------------------------------------------------
// 3x3 stride-2 conv over PRE-NORMALIZED PADDED input (pad=1, layout above).
// Thread = 2x2 outputs x COPT channels. Vectorized row loads: per footprint
// row, 1 scalar LDG + 1 aligned LDG.128 (base col 2*ow0+4 is 16B-aligned).
// Fused stats partials on OUTPUT into g_ps.
// ---------------------------------------------------------------------------
template <int CIN, int COUT, int COPT, int HIN, int WIN, int NT>
__global__ void __launch_bounds__(NT) conv_s2_t(const float* __restrict__ xpad,
                                                const float* __restrict__ w,
                                                const float* __restrict__ bias,
                                                float* __restrict__ y) {
    constexpr int HOUT = HIN / 2, WOUT = WIN / 2;
    constexpr int TW = WOUT / 2;
    constexpr int WP = WIN + 8;
    constexpr int PS = (HIN + 2) * WP;
    constexpr int CHUNK = (CIN < 64) ? CIN : 64;
    constexpr int V = COPT / 4;
    __shared__ __align__(16) float wsm[CHUNK * 9 * COPT];
    __shared__ float ssm[NT / 32][COPT], qsm[NT / 32][COPT];

    int t = blockIdx.x * NT + threadIdx.x;
    int cog = blockIdx.y % (COUT / COPT);
    int n = blockIdx.y / (COUT / COPT);
    int oh0 = (t / TW) * 2, ow0 = (t % TW) * 2;
    int lane = threadIdx.x & 31, wrp = threadIdx.x >> 5;

    float acc[4 * COPT];
#pragma unroll
    for (int i = 0; i < 4 * COPT; i++) acc[i] = 0.f;

    // base col = 2*ow0 + 3 (pad slot 4 + first footprint col 2*ow0-1)
    const float* xbase = xpad + (size_t)n * CIN * PS + (size_t)(oh0 * 2) * WP + ow0 * 2 + 3;

#pragma unroll 1
    for (int c0 = 0; c0 < CIN; c0 += CHUNK) {
        __syncthreads();
        for (int i = threadIdx.x; i < CHUNK * 9 * COPT; i += NT) {
            int ci_l = i / (9 * COPT);
            int rem = i - ci_l * (9 * COPT);
            int tap = rem / COPT;
            int u = rem - tap * COPT;
            wsm[i] = w[((size_t)(cog * COPT + u) * CIN + c0 + ci_l) * 9 + tap];
        }
        __syncthreads();
#pragma unroll 1
        for (int ci_l = 0; ci_l < CHUNK; ci_l++) {
            const float* xp = xbase + (size_t)(c0 + ci_l) * PS;

            // vectorized footprint: per row 1 scalar + 1 aligned float4
            float xv[25];
#pragma unroll
            for (int r = 0; r < 5; r++) {
                const float* xr = xp + r * WP;
                xv[r * 5 + 0] = xr[0];
                float4 q4 = *reinterpret_cast<const float4*>(xr + 1);
                xv[r * 5 + 1] = q4.x;
                xv[r * 5 + 2] = q4.y;
                xv[r * 5 + 3] = q4.z;
                xv[r * 5 + 4] = q4.w;
            }

            const float4* wp4 = reinterpret_cast<const float4*>(wsm + ci_l * 9 * COPT);
#pragma unroll
            for (int kh = 0; kh < 3; kh++) {
#pragma unroll
                for (int kw = 0; kw < 3; kw++) {
#pragma unroll
                    for (int v = 0; v < V; v++) {
                        float4 wq = wp4[(kh * 3 + kw) * V + v];
                        float wa[4] = {wq.x, wq.y, wq.z, wq.w};
#pragma unroll
                        for (int j = 0; j < 4; j++) {
#pragma unroll
                            for (int orow = 0; orow < 2; orow++)
#pragma unroll
                                for (int oc = 0; oc < 2; oc++)
                                    acc[(orow * 2 + oc) * COPT + v * 4 + j] =
                                        fmaf(xv[(2 * orow + kh) * 5 + 2 * oc + kw], wa[j],
                                             acc[(orow * 2 + oc) * COPT + v * 4 + j]);
                        }
                    }
                }
            }
        }
    }
#pragma unroll
    for (int u = 0; u < COPT; u++) {
        float bv = bias[cog * COPT + u];
#pragma unroll
        for (int p = 0; p < 4; p++) acc[p * COPT + u] += bv;
    }
    size_t obase = (size_t)(n * COUT + cog * COPT) * HOUT * WOUT + (size_t)oh0 * WOUT + ow0;
#pragma unroll
    for (int u = 0; u < COPT; u++) {
#pragma unroll
        for (int orow = 0; orow < 2; orow++) {
            float* yp = y + obase + (size_t)u * HOUT * WOUT + (size_t)orow * WOUT;
            float2 v;
            v.x = acc[(orow * 2 + 0) * COPT + u];
            v.y = acc[(orow * 2 + 1) * COPT + u];
            *reinterpret_cast<float2*>(yp) = v;
        }
    }
#pragma unroll
    for (int u = 0; u < COPT; u++) {
        float s = 0.f, q = 0.f;
#pragma unroll
        for (int p = 0; p < 4; p++) {
            float v = acc[p * COPT + u];
            s += v;
            q += v * v;
        }
        for (int o = 16; o; o >>= 1) {
            s += __shfl_down_sync(0xffffffffu, s, o);
            q += __shfl_down_sync(0xffffffffu, q, o);
        }
        if (lane == 0) { ssm[wrp][u] = s; qsm[wrp][u] = q; }
    }
    __syncthreads();
    if (threadIdx.x < COPT) {
        float s = 0.f, q = 0.f;
#pragma unroll
        for (int wpp = 0; wpp < NT / 32; wpp++) { s += ssm[wpp][threadIdx.x]; q += qsm[wpp][threadIdx.x]; }
        int plane = n * COUT + cog * COPT + threadIdx.x;
        g_ps[(size_t)plane * MAXB + blockIdx.x] = make_float2(s, q);
    }
}

// ---------------------------------------------------------------------------
// ConvTranspose2d k=3 s=2 p=1 op=1 over PRE-NORMALIZED PADDED input (pad=1).
// TS x TS tile, weight layout (CIN, COUT, 3, 3). No predicates, no norm math.
// ---------------------------------------------------------------------------
template <int CIN, int COUT, int COPT, int TS, int HIN, int WIN, int NT>
__global__ void __launch_bounds__(NT) deconv_t(const float* __restrict__ xpad,
                                               const float* __restrict__ w,
                                               const float* __restrict__ bias,
                                               float* __restrict__ y) {
    constexpr int HOUT = HIN * 2, WOUT = WIN * 2;
    constexpr int TW = WOUT / TS;
    constexpr int SUB = TS / 2;
    constexpr int WP = WIN + 8;
    constexpr int PS = (HIN + 2) * WP;
    constexpr int CHUNK = (CIN < 64) ? CIN : 64;
    constexpr int V = COPT / 4;
    __shared__ __align__(16) float wsm[CHUNK * 9 * COPT];
    __shared__ float ssm[NT / 32][COPT], qsm[NT / 32][COPT];

    int t = blockIdx.x * NT + threadIdx.x;
    int cog = blockIdx.y % (COUT / COPT);
    int n = blockIdx.y / (COUT / COPT);
    int oh0 = (t / TW) * TS, ow0 = (t % TW) * TS;
    int i0 = oh0 >> 1, j0 = ow0 >> 1;
    int lane = threadIdx.x & 31, wrp = threadIdx.x >> 5;

    float acc[TS * TS * COPT];
#pragma unroll
    for (int i = 0; i < TS * TS * COPT; i++) acc[i] = 0.f;

    const float* xbase = xpad + (size_t)n * CIN * PS + (size_t)(i0 + 1) * WP + j0 + 4;

#pragma unroll 1
    for (int c0 = 0; c0 < CIN; c0 += CHUNK) {
        __syncthreads();
        for (int i = threadIdx.x; i < CHUNK * 9 * COPT; i += NT) {
            int ci_l = i / (9 * COPT);
            int rem = i - ci_l * (9 * COPT);
            int tap = rem / COPT;
            int u = rem - tap * COPT;
            wsm[i] = w[((size_t)(c0 + ci_l) * COUT + cog * COPT + u) * 9 + tap];
        }
        __syncthreads();
#pragma unroll 1
        for (int ci_l = 0; ci_l < CHUNK; ci_l++) {
            const float* xp = xbase + (size_t)(c0 + ci_l) * PS;
            float xr[(SUB + 1) * (SUB + 1)];
#pragma unroll
            for (int r = 0; r <= SUB; r++)
#pragma unroll
                for (int c = 0; c <= SUB; c++)
                    xr[r * (SUB + 1) + c] = xp[r * WP + c];

#pragma unroll
            for (int kh = 0; kh < 3; kh++) {
                int orl = (kh == 1) ? 0 : 1;
                int xro = (kh == 0) ? 1 : 0;
#pragma unroll
                for (int kw = 0; kw < 3; kw++) {
                    int ocl = (kw == 1) ? 0 : 1;
                    int xco = (kw == 0) ? 1 : 0;
                    const float4* wp4 =
                        reinterpret_cast<const float4*>(wsm + (ci_l * 9 + kh * 3 + kw) * COPT);
#pragma unroll
                    for (int v = 0; v < V; v++) {
                        float4 wq = wp4[v];
                        float wa[4] = {wq.x, wq.y, wq.z, wq.w};
#pragma unroll
                        for (int j = 0; j < 4; j++) {
#pragma unroll
                            for (int a = 0; a < SUB; a++)
#pragma unroll
                                for (int b = 0; b < SUB; b++)
                                    acc[((2 * a + orl) * TS + (2 * b + ocl)) * COPT + v * 4 + j] =
                                        fmaf(xr[(a + xro) * (SUB + 1) + (b + xco)], wa[j],
                                             acc[((2 * a + orl) * TS + (2 * b + ocl)) * COPT + v * 4 + j]);
                        }
                    }
                }
            }
        }
    }
#pragma unroll
    for (int u = 0; u < COPT; u++) {
        float bv = bias[cog * COPT + u];
#pragma unroll
        for (int p = 0; p < TS * TS; p++) acc[p * COPT + u] += bv;
    }
    size_t obase = (size_t)(n * COUT + cog * COPT) * HOUT * WOUT + (size_t)oh0 * WOUT + ow0;
#pragma unroll
    for (int u = 0; u < COPT; u++) {
#pragma unroll
        for (int orow = 0; orow < TS; orow++) {
            float* yp = y + obase + (size_t)u * HOUT * WOUT + (size_t)orow * WOUT;
            float2 v;
            v.x = acc[(orow * TS + 0) * COPT + u];
            v.y = acc[(orow * TS + 1) * COPT + u];
            *reinterpret_cast<float2*>(yp) = v;
        }
    }
#pragma unroll
    for (int u = 0; u < COPT; u++) {
        float s = 0.f, q = 0.f;
#pragma unroll
        for (int p = 0; p < TS * TS; p++) {
            float v = acc[p * COPT + u];
            s += v;
            q += v * v;
        }
        for (int o = 16; o; o >>= 1) {
            s += __shfl_down_sync(0xffffffffu, s, o);
            q += __shfl_down_sync(0xffffffffu, q, o);
        }
        if (lane == 0) { ssm[wrp][u] = s; qsm[wrp][u] = q; }
    }
    __syncthreads();
    if (threadIdx.x < COPT) {
        float s = 0.f, q = 0.f;
#pragma unroll
        for (int wpp = 0; wpp < NT / 32; wpp++) { s += ssm[wpp][threadIdx.x]; q += qsm[wpp][threadIdx.x]; }
        int plane = n * COUT + cog * COPT + threadIdx.x;
        g_ps[(size_t)plane * MAXB + blockIdx.x] = make_float2(s, q);
    }
}

// ---------------------------------------------------------------------------
// conv0: reflect-pad 3, 7x7, 3->16. Thread = 1 row x 4 cols, all 16 co.
// Reads raw global input (reflect handled inline; only 3 channels).
// ---------------------------------------------------------------------------
__global__ void __launch_bounds__(256) conv7_first(const float* __restrict__ x,
                                                   const float* __restrict__ w,
                                                   const float* __restrict__ bias,
                                                   float* __restrict__ y) {
    __shared__ __align__(16) float wsm[3 * 49 * 16];
    __shared__ float ssm[8][16], qsm[8][16];
    for (int i = threadIdx.x; i < 3 * 49 * 16; i += 256) {
        int ci = i / (49 * 16);
        int rem = i - ci * (49 * 16);
        int tap = rem / 16;
        int co = rem - tap * 16;
        wsm[i] = w[(co * 3 + ci) * 49 + tap];
    }
    __syncthreads();

    int t = blockIdx.x * 256 + threadIdx.x;
    int n = blockIdx.y;
    int oh = t >> 7;
    int ow0 = (t & 127) * 4;

    int iwI[10];
#pragma unroll
    for (int c = 0; c < 10; c++) iwI[c] = refl(ow0 - 3 + c, WW);
    bool wInt = (ow0 >= 4) && (ow0 + 7 <= WW - 1);

    float acc[4 * 16];
#pragma unroll
    for (int i = 0; i < 4 * 16; i++) acc[i] = 0.f;

#pragma unroll 1
    for (int ci = 0; ci < 3; ci++) {
        const float* xp = x + (size_t)(n * 3 + ci) * HH * WW;
#pragma unroll 1
        for (int kh = 0; kh < 7; kh++) {
            const float* xr = xp + (size_t)refl(oh + kh - 3, HH) * WW;
            float xv[10];
            if (wInt) {
                const float* b = xr + ow0;
                float4 qa = *reinterpret_cast<const float4*>(b - 4);
                float4 qb = *reinterpret_cast<const float4*>(b);
                float4 qc = *reinterpret_cast<const float4*>(b + 4);
                xv[0] = qa.y; xv[1] = qa.z; xv[2] = qa.w;
                xv[3] = qb.x; xv[4] = qb.y; xv[5] = qb.z; xv[6] = qb.w;
                xv[7] = qc.x; xv[8] = qc.y; xv[9] = qc.z;
            } else {
#pragma unroll
                for (int c = 0; c < 10; c++) xv[c] = xr[iwI[c]];
            }
            const float4* wb4 = reinterpret_cast<const float4*>(wsm + (ci * 49 + kh * 7) * 16);
#pragma unroll
            for (int kw = 0; kw < 7; kw++) {
#pragma unroll
                for (int v = 0; v < 4; v++) {
                    float4 wq = wb4[kw * 4 + v];
                    float wa[4] = {wq.x, wq.y, wq.z, wq.w};
#pragma unroll
                    for (int j = 0; j < 4; j++) {
#pragma unroll
                        for (int sc = 0; sc < 4; sc++)
                            acc[sc * 16 + v * 4 + j] = fmaf(xv[sc + kw], wa[j], acc[sc * 16 + v * 4 + j]);
                    }
                }
            }
        }
    }
#pragma unroll
    for (int co = 0; co < 16; co++) {
        float bv = bias[co];
#pragma unroll
        for (int sc = 0; sc < 4; sc++) acc[sc * 16 + co] += bv;
    }
#pragma unroll
    for (int co = 0; co < 16; co++) {
        float* yp = y + (size_t)(n * 16 + co) * HH * WW + (size_t)oh * WW + ow0;
        float4 v0;
        v0.x = acc[0 * 16 + co]; v0.y = acc[1 * 16 + co];
        v0.z = acc[2 * 16 + co]; v0.w = acc[3 * 16 + co];
        *reinterpret_cast<float4*>(yp) = v0;
    }
    int lane = threadIdx.x & 31, wrp = threadIdx.x >> 5;
#pragma unroll
    for (int co = 0; co < 16; co++) {
        float s = 0.f, q = 0.f;
#pragma unroll
        for (int sc = 0; sc < 4; sc++) {
            float v = acc[sc * 16 + co];
            s += v;
            q += v * v;
        }
        for (int o = 16; o; o >>= 1) {
            s += __shfl_down_sync(0xffffffffu, s, o);
            q += __shfl_down_sync(0xffffffffu, q, o);
        }
        if (lane == 0) { ssm[wrp][co] = s; qsm[wrp][co] = q; }
    }
    __syncthreads();
    if (threadIdx.x < 16) {
        float s = 0.f, q = 0.f;
#pragma unroll
        for (int wpp = 0; wpp < 8; wpp++) { s += ssm[wpp][threadIdx.x]; q += qsm[wpp][threadIdx.x]; }
        int plane = n * 16 + threadIdx.x;
        g_ps[(size_t)plane * MAXB + blockIdx.x] = make_float2(s, q);
    }
}

// ---------------------------------------------------------------------------
// conv9: 7x7, 16->3 over PRE-NORMALIZED REFLECT-PADDED input (pad=3), tanh.
// Vectorized row loads: 3 scalars + 3 aligned LDG.128 per 14-wide row.
// ---------------------------------------------------------------------------
__global__ void __launch_bounds__(256) conv7_last(const float* __restrict__ xpad,
                                                  const float* __restrict__ w,
                                                  const float* __restrict__ bias,
                                                  float* __restrict__ y) {
    constexpr int WP = WW + 8;               // 520
    constexpr int PS = (HH + 6) * WP;        // 518*520
    __shared__ float wsm[16 * 49 * 3];
    for (int i = threadIdx.x; i < 16 * 49 * 3; i += 256) {
        int ci = i / (49 * 3);
        int rem = i - ci * (49 * 3);
        int tap = rem / 3;
        int co = rem - tap * 3;
        wsm[i] = w[(co * 16 + ci) * 49 + tap];
    }
    __syncthreads();

    int t = blockIdx.x * 256 + threadIdx.x;
    int n = blockIdx.y;
    int oh = t >> 6;
    int ow0 = (t & 63) * 8;

    float acc[8 * 3];
#pragma unroll
    for (int i = 0; i < 8 * 3; i++) acc[i] = 0.f;

    // base col = ow0 + 1 (pad slot 4 + first footprint col ow0-3)
    const float* xbase = xpad + (size_t)n * 16 * PS + (size_t)oh * WP + ow0 + 1;

#pragma unroll 1
    for (int ci = 0; ci < 16; ci++) {
        const float* xp = xbase + (size_t)ci * PS;
#pragma unroll 1
        for (int kh = 0; kh < 7; kh++) {
            const float* xr = xp + kh * WP;
            float xv[14];
            // xr+3 is 16B-aligned (col ow0+4, ow0 multiple of 8)
            xv[0] = xr[0]; xv[1] = xr[1]; xv[2] = xr[2];
            float4 qa = *reinterpret_cast<const float4*>(xr + 3);
            float4 qb = *reinterpret_cast<const float4*>(xr + 7);
            float4 qc = *reinterpret_cast<const float4*>(xr + 11);
            xv[3] = qa.x;  xv[4] = qa.y;  xv[5] = qa.z;  xv[6] = qa.w;
            xv[7] = qb.x;  xv[8] = qb.y;  xv[9] = qb.z;  xv[10] = qb.w;
            xv[11] = qc.x; xv[12] = qc.y; xv[13] = qc.z;
            const float* wb = wsm + (ci * 49 + kh * 7) * 3;
#pragma unroll
            for (int kw = 0; kw < 7; kw++) {
#pragma unroll
                for (int co = 0; co < 3; co++) {
                    float wvv = wb[kw * 3 + co];
#pragma unroll
                    for (int sc = 0; sc < 8; sc++)
                        acc[sc * 3 + co] = fmaf(xv[sc + kw], wvv, acc[sc * 3 + co]);
                }
            }
        }
    }
#pragma unroll
    for (int co = 0; co < 3; co++) {
        float bv = bias[co];
        float* yp = y + (size_t)(n * 3 + co) * HH * WW + (size_t)oh * WW + ow0;
        float4 v0, v1;
        v0.x = tanhf(acc[0 * 3 + co] + bv); v0.y = tanhf(acc[1 * 3 + co] + bv);
        v0.z = tanhf(acc[2 * 3 + co] + bv); v0.w = tanhf(acc[3 * 3 + co] + bv);
        v1.x = tanhf(acc[4 * 3 + co] + bv); v1.y = tanhf(acc[5 * 3 + co] + bv);
        v1.z = tanhf(acc[6 * 3 + co] + bv); v1.w = tanhf(acc[7 * 3 + co] + bv);
        ((float4*)yp)[0] = v0;
        ((float4*)yp)[1] = v1;
    }
}

// ---------------------------------------------------------------------------
// Segment mean: (label, slice) partials, deterministic, then combine.
// ---------------------------------------------------------------------------
__global__ void segpart_k(const float* __restrict__ feats, const int* __restrict__ inst) {
    int lab = blockIdx.x, slice = blockIdx.y;
    const int HWp = HH * WW;
    const int per = BB * HWp / 8;
    int start = slice * per;
    float c0 = 0.f, c1 = 0.f, c2 = 0.f, cnt = 0.f;
    for (int p = start + threadIdx.x; p < start + per; p += 256) {
        if (inst[p] == lab) {
            int n = p / HWp;
            int hw = p - n * HWp;
            const float* f = feats + (size_t)n * 3 * HWp + hw;
            c0 += f[0];
            c1 += f[HWp];
            c2 += f[2 * HWp];
            cnt += 1.f;
        }
    }
    __shared__ float s0[256], s1[256], s2[256], sc[256];
    s0[threadIdx.x] = c0; s1[threadIdx.x] = c1; s2[threadIdx.x] = c2; sc[threadIdx.x] = cnt;
    __syncthreads();
    for (int o = 128; o > 0; o >>= 1) {
        if (threadIdx.x < o) {
            s0[threadIdx.x] += s0[threadIdx.x + o];
            s1[threadIdx.x] += s1[threadIdx.x + o];
            s2[threadIdx.x] += s2[threadIdx.x + o];
            sc[threadIdx.x] += sc[threadIdx.x + o];
        }
        __syncthreads();
    }
    if (threadIdx.x == 0) {
        float* q = &g_part[(lab * 8 + slice) * 4];
        q[0] = s0[0]; q[1] = s1[0]; q[2] = s2[0]; q[3] = sc[0];
    }
}

__global__ void segfin_k() {
    int lab = threadIdx.x;
    if (lab >= NUM_INST) return;
    float s0 = 0.f, s1 = 0.f, s2 = 0.f, c = 0.f;
    for (int sl = 0; sl < 8; sl++) {
        const float* p = &g_part[(lab * 8 + sl) * 4];
        s0 += p[0]; s1 += p[1]; s2 += p[2]; c += p[3];
    }
    float d = fmaxf(c, 1.f);
    g_means[lab * 3 + 0] = s0 / d;
    g_means[lab * 3 + 1] = s1 / d;
    g_means[lab * 3 + 2] = s2 / d;
}

__global__ void gather_k(const int* __restrict__ inst, float* __restrict__ out) {
    int idx = blockIdx.x * 256 + threadIdx.x;
    const int Q = HH * WW / 4;
    if (idx >= BB * Q) return;
    int n = idx / Q, h4 = idx - n * Q;
    int4 lb = ((const int4*)inst)[(size_t)n * Q + h4];
#pragma unroll
    for (int c = 0; c < 3; c++) {
        float4 v;
        v.x = g_means[lb.x * 3 + c];
        v.y = g_means[lb.y * 3 + c];
        v.z = g_means[lb.z * 3 + c];
        v.w = g_means[lb.w * 3 + c];
        ((float4*)out)[(size_t)(n * 3 + c) * Q + h4] = v;
    }
}

// ---------------------------------------------------------------------------
extern "C" void kernel_launch(void* const* d_in, const int* in_sizes, int n_in,
                              void* d_out, int out_size) {
    const float* input = (const float*)d_in[0];
    const int* inst = (const int*)d_in[1];
    const float* w0 = (const float*)d_in[2];  const float* b0 = (const float*)d_in[3];
    const float* w1 = (const float*)d_in[4];  const float* b1 = (const float*)d_in[5];
    const float* w2 = (const float*)d_in[6];  const float* b2 = (const float*)d_in[7];
    const float* w3 = (const float*)d_in[8];  const float* b3 = (const float*)d_in[9];
    const float* w4 = (const float*)d_in[10]; const float* b4 = (const float*)d_in[11];
    const float* w5 = (const float*)d_in[12]; const float* b5 = (const float*)d_in[13];
    const float* w6 = (const float*)d_in[14]; const float* b6 = (const float*)d_in[15];
    const float* w7 = (const float*)d_in[16]; const float* b7 = (const float*)d_in[17];
    const float* w8 = (const float*)d_in[18]; const float* b8 = (const float*)d_in[19];
    const float* w9 = (const float*)d_in[20]; const float* b9 = (const float*)d_in[21];
    float* out = (float*)d_out;

    float* bufA; float* bufB; float* bufP;
    cudaGetSymbolAddress((void**)&bufA, g_bufA);
    cudaGetSymbolAddress((void**)&bufB, g_bufB);
    cudaGetSymbolAddress((void**)&bufP, g_bufP);

    const float i512 = 1.f / (512.f * 512.f);
    const float i256 = 1.f / (256.f * 256.f);
    const float i128 = 1.f / (128.f * 128.f);
    const float i64  = 1.f / (64.f * 64.f);
    const float i32  = 1.f / (32.f * 32.f);

    // conv0: raw input -> bufA [4,16,512,512], 256 stats partials/plane
    conv7_first<<<dim3(256, BB), 256>>>(input, w0, b0, bufA);
    normpad_k<<<dim3(514, BB * 16), 128>>>(bufA, bufP, 512, 512, 1, 0, 256, i512);

    conv_s2_t<16, 32, 8, 512, 512, 256><<<dim3(64, BB * 4), 256>>>(bufP, w1, b1, bufB);
    normpad_k<<<dim3(258, BB * 32), 64>>>(bufB, bufP, 256, 256, 1, 0, 64, i256);

    conv_s2_t<32, 64, 8, 256, 256, 256><<<dim3(16, BB * 8), 256>>>(bufP, w2, b2, bufA);
    normpad_k<<<dim3(130, BB * 64), 32>>>(bufA, bufP, 128, 128, 1, 0, 16, i128);

    conv_s2_t<64, 128, 4, 128, 128, 256><<<dim3(4, BB * 32), 256>>>(bufP, w3, b3, bufB);
    normpad_k<<<dim3(66, BB * 128), 32>>>(bufB, bufP, 64, 64, 1, 0, 4, i64);

    conv_s2_t<128, 256, 4, 64, 64, 256><<<dim3(1, BB * 64), 256>>>(bufP, w4, b4, bufA);
    normpad_k<<<dim3(34, BB * 256), 32>>>(bufA, bufP, 32, 32, 1, 0, 1, i32);

    deconv_t<256, 128, 4, 2, 32, 32, 256><<<dim3(4, BB * 32), 256>>>(bufP, w5, b5, bufB);
    normpad_k<<<dim3(66, BB * 128), 32>>>(bufB, bufP, 64, 64, 1, 0, 4, i64);

    deconv_t<128, 64, 8, 2, 64, 64, 256><<<dim3(16, BB * 8), 256>>>(bufP, w6, b6, bufA);
    normpad_k<<<dim3(130, BB * 64), 32>>>(bufA, bufP, 128, 128, 1, 0, 16, i128);

    deconv_t<64, 32, 8, 2, 128, 128, 256><<<dim3(64, BB * 4), 256>>>(bufP, w7, b7, bufB);
    normpad_k<<<dim3(258, BB * 32), 64>>>(bufB, bufP, 256, 256, 1, 0, 64, i256);

    deconv_t<32, 16, 8, 2, 256, 256, 256><<<dim3(256, BB * 2), 256>>>(bufP, w8, b8, bufA);
    // reflect-pad P=3 normalized input for conv9
    normpad_k<<<dim3(518, BB * 16), 128>>>(bufA, bufP, 512, 512, 3, 1, 256, i512);

    // conv9 + tanh: bufP -> bufB [4,3,512,512]
    conv7_last<<<dim3(128, BB), 256>>>(bufP, w9, b9, bufB);

    // segment mean + gather
    segpart_k<<<dim3(NUM_INST, 8), 256>>>(bufB, inst);
    segfin_k<<<1, 32>>>();
    gather_k<<<(BB * HH * WW / 4 + 255) / 256, 256>>>(inst, out);
}